// round 11
// baseline (speedup 1.0000x reference)
#include <cuda_runtime.h>
#include <cuda_fp16.h>

// Problem constants (match reference)
#define BB 32
#define LL 4096
#define DD 128
#define NN1 4      // N-1 context slots
#define VV 128

// fp16 lookup table: T[k][tok][v], 4*128*128 halves = 128 KB.
// MUST stay L1-resident in phase B -> this kernel uses ZERO shared memory
// (any static smem forces an L1 carveout for the whole kernel; round 10's
// 13 KB smem shrank L1D below the table size and doubled runtime).
// Bias is pre-folded into the k=0 slice.
__device__ __half g_Th[NN1 * VV * VV];

// Monotone build-completion counter (512 warp-units). Never reset: on graph
// replays it is already >= 512, so no CTA spins and builders rebuild
// byte-identical values concurrently with phase B (harmless). First launch
// gates properly; 64 builder CTAs always fit in wave 1 -> no deadlock.
__device__ int g_done;

#define BUILD_WARPS 512            // 4 k-slices x 128 v rows
#define BUILD_CTAS  (BUILD_WARPS / 8)   // 64

__device__ __forceinline__ float4 combine4(const uint2& u0, const uint2& u1,
                                           const uint2& u2, const uint2& u3) {
    __half2 lo = __hadd2(__hadd2(*(const __half2*)&u0.x, *(const __half2*)&u1.x),
                         __hadd2(*(const __half2*)&u2.x, *(const __half2*)&u3.x));
    __half2 hi = __hadd2(__hadd2(*(const __half2*)&u0.y, *(const __half2*)&u1.y),
                         __hadd2(*(const __half2*)&u2.y, *(const __half2*)&u3.y));
    float2 flo = __half22float2(lo);
    float2 fhi = __half22float2(hi);
    return make_float4(flo.x, flo.y, fhi.x, fhi.y);
}

// ---------------------------------------------------------------------------
// Fused kernel. grid = 8192 CTAs x 256 threads, ZERO shared memory.
//   Phase A (CTAs 0..63, warp-granular): warp = (k, v) computes
//     T[k][tok][v] = sum_d emb[tok][d] * W[v][k*128+d]  (+ b[v] at k=0)
//   via per-lane float4 W slice (registers) + coalesced emb loads +
//   5-level shfl_xor butterfly; lane 0 stores fp16.
//   Barrier: volatile-load poll of g_done (no-op on replays).
//   Phase B (all CTAs): gather-sum, one warp per 2 consecutive positions.
// ---------------------------------------------------------------------------
__global__ void __launch_bounds__(256, 8)
fused_ngram_kernel(const int* __restrict__ x,
                   const float* __restrict__ emb,
                   const float* __restrict__ W,
                   const float* __restrict__ bvec,
                   float* __restrict__ out) {
    const int tid  = threadIdx.x;
    const int lane = tid & 31;
    const int wid  = tid >> 5;

    // ---------------- Phase A: table build (CTAs 0..63) ----------------
    if (blockIdx.x < BUILD_CTAS) {
        const int unit = blockIdx.x * 8 + wid;     // 0..511
        const int k = unit & 3;
        const int v = unit >> 2;                   // 0..127

        // Lane's 4-wide slice of W[v][k*128 .. k*128+127] (coalesced, once).
        const float4 w4 = __ldg(reinterpret_cast<const float4*>(
                               W + (size_t)v * (NN1 * DD) + k * DD) + lane);
        const float bias = (k == 0) ? __ldg(&bvec[v]) : 0.0f;

#pragma unroll 4
        for (int tok = 0; tok < VV; tok++) {
            float4 e4 = __ldg(reinterpret_cast<const float4*>(
                              emb + (size_t)tok * DD) + lane);
            float p = w4.x * e4.x + w4.y * e4.y + w4.z * e4.z + w4.w * e4.w;
            p += __shfl_xor_sync(0xFFFFFFFFu, p, 16);
            p += __shfl_xor_sync(0xFFFFFFFFu, p, 8);
            p += __shfl_xor_sync(0xFFFFFFFFu, p, 4);
            p += __shfl_xor_sync(0xFFFFFFFFu, p, 2);
            p += __shfl_xor_sync(0xFFFFFFFFu, p, 1);
            if (lane == 0)
                g_Th[(k * VV + tok) * VV + v] = __float2half_rn(p + bias);
        }
        __threadfence();                           // publish table stores
        if (lane == 0) atomicAdd(&g_done, 1);      // 512 arrivals total
    }

    // ------------- Barrier: wait for full table (load-based poll) ----------
    if (tid == 0) {
        const volatile int* flag = &g_done;
        if (*flag < BUILD_WARPS) {                 // first launch only
            while (*flag < BUILD_WARPS) __nanosleep(128);
        }
        __threadfence();                           // acquire table stores
    }
    __syncthreads();

    // ---------------- Phase B: gather-sum ----------------
    const int warp = blockIdx.x * 8 + wid;
    const int pos0 = warp << 1;                 // two consecutive positions
    const int b  = pos0 >> 12;                  // / 4096
    const int j0 = pos0 & (LL - 1);             // % 4096 (even)

    float4* o = reinterpret_cast<float4*>(out + (size_t)pos0 * VV);

    if (j0 < NN1) {                             // j0 in {0,2}: bias only
        float4 bb = reinterpret_cast<const float4*>(bvec)[lane];
        o[lane]      = bb;
        o[32 + lane] = bb;
        return;
    }

    const int* xr = x + b * LL + (j0 - NN1);
    const int t0 = __ldg(xr + 0);
    const int t1 = __ldg(xr + 1);
    const int t2 = __ldg(xr + 2);
    const int t3 = __ldg(xr + 3);
    const int t4 = __ldg(xr + 4);

    const uint2* T = reinterpret_cast<const uint2*>(g_Th);   // 32 uint2 per row
    // position j0: tokens t0..t3; position j0+1: tokens t1..t4
    uint2 a0 = __ldg(&T[((0 * VV + t0) << 5) + lane]);
    uint2 a1 = __ldg(&T[((1 * VV + t1) << 5) + lane]);
    uint2 a2 = __ldg(&T[((2 * VV + t2) << 5) + lane]);
    uint2 a3 = __ldg(&T[((3 * VV + t3) << 5) + lane]);
    uint2 c0 = __ldg(&T[((0 * VV + t1) << 5) + lane]);
    uint2 c1 = __ldg(&T[((1 * VV + t2) << 5) + lane]);
    uint2 c2 = __ldg(&T[((2 * VV + t3) << 5) + lane]);
    uint2 c3 = __ldg(&T[((3 * VV + t4) << 5) + lane]);

    o[lane]      = combine4(a0, a1, a2, a3);
    o[32 + lane] = combine4(c0, c1, c2, c3);
}

// ---------------------------------------------------------------------------
// Launch. Inputs (metadata order): x(int32 B*L), emb(f32 V*D), W(f32 V*4D),
// b(f32 V). Output: f32 B*L*V. Single fused kernel launch.
// ---------------------------------------------------------------------------
extern "C" void kernel_launch(void* const* d_in, const int* in_sizes, int n_in,
                              void* d_out, int out_size) {
    const int*   x    = (const int*)d_in[0];
    const float* emb  = (const float*)d_in[1];
    const float* W    = (const float*)d_in[2];
    const float* bvec = (const float*)d_in[3];
    float* out = (float*)d_out;

    const int positions = BB * LL;              // 131072
    const int warps = positions / 2;            // 65536
    const int blocks = warps / 8;               // 8192 (8 warps/block, exact)
    fused_ngram_kernel<<<blocks, 256>>>(x, emb, W, bvec, out);
}

// round 12
// speedup vs baseline: 1.2145x; 1.2145x over previous
#include <cuda_runtime.h>
#include <cuda_fp16.h>

// Problem constants (match reference)
#define BB 32
#define LL 4096
#define DD 128
#define NN1 4      // N-1 context slots
#define VV 128

// fp16 lookup table: T[k][tok][v], 4*128*128 halves = 128 KB. Zero smem in
// this kernel -> full 228 KB L1 carveout -> table L1-resident, PROVIDED the
// loads stay non-coherent: because this kernel also WRITES g_Th, nvcc demotes
// __ldg to a coherent (L1-bypassing) load — rounds 9-11 regression. We force
// ld.global.nc via inline PTX. Bias pre-folded into the k=0 slice.
__device__ __half g_Th[NN1 * VV * VV];

// Monotone build-completion counter (1024 warp-units). Never reset: replays
// see it >= 1024 and skip the spin; builders redundantly rewrite
// byte-identical values (harmless, deterministic output). First launch gates.
__device__ int g_done;

#define BUILD_UNITS 1024           // 4 k * 128 v * 2 tok-halves
#define BUILD_CTAS  (BUILD_UNITS / 8)   // 128 (always inside wave 1)

// Forced non-coherent (L1-cached) 8-byte table load.
__device__ __forceinline__ uint2 ldg_nc_u2(const uint2* p) {
    uint2 r;
    asm("ld.global.nc.v2.u32 {%0,%1}, [%2];" : "=r"(r.x), "=r"(r.y) : "l"(p));
    return r;
}

__device__ __forceinline__ float4 combine4(const uint2& u0, const uint2& u1,
                                           const uint2& u2, const uint2& u3) {
    __half2 lo = __hadd2(__hadd2(*(const __half2*)&u0.x, *(const __half2*)&u1.x),
                         __hadd2(*(const __half2*)&u2.x, *(const __half2*)&u3.x));
    __half2 hi = __hadd2(__hadd2(*(const __half2*)&u0.y, *(const __half2*)&u1.y),
                         __hadd2(*(const __half2*)&u2.y, *(const __half2*)&u3.y));
    float2 flo = __half22float2(lo);
    float2 fhi = __half22float2(hi);
    return make_float4(flo.x, flo.y, fhi.x, fhi.y);
}

__device__ __forceinline__ float warp_sum(float p) {
    p += __shfl_xor_sync(0xFFFFFFFFu, p, 16);
    p += __shfl_xor_sync(0xFFFFFFFFu, p, 8);
    p += __shfl_xor_sync(0xFFFFFFFFu, p, 4);
    p += __shfl_xor_sync(0xFFFFFFFFu, p, 2);
    p += __shfl_xor_sync(0xFFFFFFFFu, p, 1);
    return p;
}

// ---------------------------------------------------------------------------
// Fused kernel. grid = 8192 CTAs x 256 threads, ZERO shared memory.
//   Phase A (CTAs 0..127, warp-granular): unit = (k, v, tok-half); warp
//     computes 64 table entries via register-resident W slice + coalesced emb
//     loads + 4-way-batched shfl reductions (pipelined, ~2us).
//   Barrier: volatile-load poll of g_done (no-op on replays).
//   Phase B (all CTAs): gather-sum, one warp per 2 consecutive positions,
//     table loads forced to ld.global.nc (L1-cached).
// ---------------------------------------------------------------------------
__global__ void __launch_bounds__(256, 8)
fused_ngram_kernel(const int* __restrict__ x,
                   const float* __restrict__ emb,
                   const float* __restrict__ W,
                   const float* __restrict__ bvec,
                   float* __restrict__ out) {
    const int tid  = threadIdx.x;
    const int lane = tid & 31;
    const int wid  = tid >> 5;

    // ---------------- Phase A: table build (CTAs 0..127) ----------------
    if (blockIdx.x < BUILD_CTAS) {
        const int unit = blockIdx.x * 8 + wid;     // 0..1023
        const int k    = unit & 3;
        const int v    = (unit >> 2) & 127;
        const int tokb = (unit >> 9) * 64;         // tok-half base

        // Lane's 4-wide slice of W[v][k*128 .. +127] (one coalesced load).
        const float4 w4 = __ldg(reinterpret_cast<const float4*>(
                               W + (size_t)v * (NN1 * DD) + k * DD) + lane);
        const float bias = (k == 0) ? __ldg(&bvec[v]) : 0.0f;

        for (int tg = 0; tg < 64; tg += 4) {       // 4-way batched reductions
            const int tok = tokb + tg;
            float4 e0 = __ldg(reinterpret_cast<const float4*>(emb + (size_t)(tok + 0) * DD) + lane);
            float4 e1 = __ldg(reinterpret_cast<const float4*>(emb + (size_t)(tok + 1) * DD) + lane);
            float4 e2 = __ldg(reinterpret_cast<const float4*>(emb + (size_t)(tok + 2) * DD) + lane);
            float4 e3 = __ldg(reinterpret_cast<const float4*>(emb + (size_t)(tok + 3) * DD) + lane);
            float p0 = w4.x * e0.x + w4.y * e0.y + w4.z * e0.z + w4.w * e0.w;
            float p1 = w4.x * e1.x + w4.y * e1.y + w4.z * e1.z + w4.w * e1.w;
            float p2 = w4.x * e2.x + w4.y * e2.y + w4.z * e2.z + w4.w * e2.w;
            float p3 = w4.x * e3.x + w4.y * e3.y + w4.z * e3.z + w4.w * e3.w;
            p0 = warp_sum(p0);
            p1 = warp_sum(p1);
            p2 = warp_sum(p2);
            p3 = warp_sum(p3);
            if (lane == 0) {
                g_Th[(k * VV + tok + 0) * VV + v] = __float2half_rn(p0 + bias);
                g_Th[(k * VV + tok + 1) * VV + v] = __float2half_rn(p1 + bias);
                g_Th[(k * VV + tok + 2) * VV + v] = __float2half_rn(p2 + bias);
                g_Th[(k * VV + tok + 3) * VV + v] = __float2half_rn(p3 + bias);
            }
        }
        __threadfence();                           // publish table stores
        if (lane == 0) atomicAdd(&g_done, 1);      // 1024 arrivals total
    }

    // ------------- Barrier: wait for full table (load-based poll) ----------
    if (tid == 0) {
        const volatile int* flag = &g_done;
        if (*flag < BUILD_UNITS) {                 // first launch only
            while (*flag < BUILD_UNITS) __nanosleep(128);
        }
        __threadfence();                           // acquire table stores
    }
    __syncthreads();

    // ---------------- Phase B: gather-sum ----------------
    const int warp = blockIdx.x * 8 + wid;
    const int pos0 = warp << 1;                 // two consecutive positions
    const int b  = pos0 >> 12;                  // / 4096
    const int j0 = pos0 & (LL - 1);             // % 4096 (even)

    float4* o = reinterpret_cast<float4*>(out + (size_t)pos0 * VV);

    if (j0 < NN1) {                             // j0 in {0,2}: bias only
        float4 bb = reinterpret_cast<const float4*>(bvec)[lane];
        o[lane]      = bb;
        o[32 + lane] = bb;
        return;
    }

    const int* xr = x + b * LL + (j0 - NN1);
    const int t0 = __ldg(xr + 0);
    const int t1 = __ldg(xr + 1);
    const int t2 = __ldg(xr + 2);
    const int t3 = __ldg(xr + 3);
    const int t4 = __ldg(xr + 4);

    const uint2* T = reinterpret_cast<const uint2*>(g_Th);   // 32 uint2 per row
    // position j0: tokens t0..t3; position j0+1: tokens t1..t4
    uint2 a0 = ldg_nc_u2(&T[((0 * VV + t0) << 5) + lane]);
    uint2 a1 = ldg_nc_u2(&T[((1 * VV + t1) << 5) + lane]);
    uint2 a2 = ldg_nc_u2(&T[((2 * VV + t2) << 5) + lane]);
    uint2 a3 = ldg_nc_u2(&T[((3 * VV + t3) << 5) + lane]);
    uint2 c0 = ldg_nc_u2(&T[((0 * VV + t1) << 5) + lane]);
    uint2 c1 = ldg_nc_u2(&T[((1 * VV + t2) << 5) + lane]);
    uint2 c2 = ldg_nc_u2(&T[((2 * VV + t3) << 5) + lane]);
    uint2 c3 = ldg_nc_u2(&T[((3 * VV + t4) << 5) + lane]);

    o[lane]      = combine4(a0, a1, a2, a3);
    o[32 + lane] = combine4(c0, c1, c2, c3);
}

// ---------------------------------------------------------------------------
// Launch. Inputs (metadata order): x(int32 B*L), emb(f32 V*D), W(f32 V*4D),
// b(f32 V). Output: f32 B*L*V. Single fused kernel launch.
// ---------------------------------------------------------------------------
extern "C" void kernel_launch(void* const* d_in, const int* in_sizes, int n_in,
                              void* d_out, int out_size) {
    const int*   x    = (const int*)d_in[0];
    const float* emb  = (const float*)d_in[1];
    const float* W    = (const float*)d_in[2];
    const float* bvec = (const float*)d_in[3];
    float* out = (float*)d_out;

    const int positions = BB * LL;              // 131072
    const int warps = positions / 2;            // 65536
    const int blocks = warps / 8;               // 8192 (8 warps/block, exact)
    fused_ngram_kernel<<<blocks, 256>>>(x, emb, W, bvec, out);
}

// round 14
// speedup vs baseline: 2.2790x; 1.8765x over previous
#include <cuda_runtime.h>
#include <cuda_fp16.h>

// Problem constants (match reference)
#define BB 32
#define LL 4096
#define DD 128
#define NN1 4      // N-1 context slots
#define VV 128

// fp16 lookup table: T[k][tok][v], 4*128*128 halves = 128 KB.
// Built by kernel 1 (global), then COPIED INTO SHARED MEMORY by each consumer
// CTA (rounds 9-12: any kernel that both writes and reads this global loses
// L1 residency). __align__(16) makes the uint4 copy in kernel 2 legal.
// Bias pre-folded into the k=0 slice.
__device__ __align__(16) __half g_Th[NN1 * VV * VV];

#define VPB 16      // v-rows per build unit
#define TPB 8       // toks per build unit
#define WPAD 4      // smem row pad (floats)

// ---------------------------------------------------------------------------
// Kernel 1 (round-5 build): T[k][tok][v] = emb[tok]·W[v,k-slice] (+b at k=0)
// grid = (8 v-groups, 16 tok-groups, 4 k) = 512 blocks, 128 threads.
// ---------------------------------------------------------------------------
__global__ void __launch_bounds__(128)
build_table_kernel(const float* __restrict__ emb,
                   const float* __restrict__ W,
                   const float* __restrict__ bvec) {
    const int v0   = blockIdx.x * VPB;
    const int tok0 = blockIdx.y * TPB;
    const int k    = blockIdx.z;

    __shared__ float sw[VPB][DD + WPAD];
    __shared__ float e[TPB][DD + WPAD];

#pragma unroll
    for (int i = 0; i < 4; i++) {
        int idx = i * 128 + threadIdx.x;           // 0..511
        int vi  = idx >> 5;
        int c   = idx & 31;
        const float4* wsrc = reinterpret_cast<const float4*>(
            W + (size_t)(v0 + vi) * (NN1 * DD) + k * DD);
        *reinterpret_cast<float4*>(&sw[vi][c * 4]) = __ldg(&wsrc[c]);
    }
    {
        const float4* esrc = reinterpret_cast<const float4*>(emb + (size_t)tok0 * DD);
#pragma unroll
        for (int i = 0; i < 2; i++) {
            int idx = i * 128 + threadIdx.x;       // 0..255
            float4 ev = __ldg(&esrc[idx]);
            int t = idx >> 5;
            int c = idx & 31;
            *reinterpret_cast<float4*>(&e[t][c * 4]) = ev;
        }
    }
    __syncthreads();

    const int vi = threadIdx.x >> 3;               // 0..15
    const int tp = threadIdx.x & 7;                // 0..7

    float acc = 0.0f;
#pragma unroll
    for (int d = 0; d < DD; d += 4) {
        float4 w  = *reinterpret_cast<const float4*>(&sw[vi][d]);
        float4 ea = *reinterpret_cast<const float4*>(&e[tp][d]);
        acc += w.x * ea.x + w.y * ea.y + w.z * ea.z + w.w * ea.w;
    }
    if (k == 0) acc += __ldg(&bvec[v0 + vi]);

    g_Th[(k * VV + tok0 + tp) * VV + v0 + vi] = __float2half_rn(acc);
}

// ---------------------------------------------------------------------------
// Kernel 2: smem-table gather-sum.
// grid = 128 CTAs x 1024 threads, dynamic smem = 128KB table + 4.2KB tokens.
// CTA owns 1024 contiguous positions of ONE batch row (1024 | 4096).
// Prologue: copy table (uint4, coalesced) + FULL 1028-token window
// (grid-stride loop — round 13's fatal bug was leaving sx[1024..1027]
// uninitialized). Main loop: warp handles 16 contiguous pairs; tokens via
// broadcast LDS, table rows via conflict-free 8B/lane LDS; only output STG
// touches global memory.
// ---------------------------------------------------------------------------
#define POS_PER_CTA 1024
#define NGRAM_CTAS  ((BB * LL) / POS_PER_CTA)   // 128
#define TBL_BYTES   (NN1 * VV * VV * 2)         // 131072
#define TOK_COUNT   (POS_PER_CTA + NN1)         // 1028
#define SMEM_BYTES  (TBL_BYTES + TOK_COUNT * 4) // 135184

__device__ __forceinline__ float4 combine4(const uint2& u0, const uint2& u1,
                                           const uint2& u2, const uint2& u3) {
    __half2 lo = __hadd2(__hadd2(*(const __half2*)&u0.x, *(const __half2*)&u1.x),
                         __hadd2(*(const __half2*)&u2.x, *(const __half2*)&u3.x));
    __half2 hi = __hadd2(__hadd2(*(const __half2*)&u0.y, *(const __half2*)&u1.y),
                         __hadd2(*(const __half2*)&u2.y, *(const __half2*)&u3.y));
    float2 flo = __half22float2(lo);
    float2 fhi = __half22float2(hi);
    return make_float4(flo.x, flo.y, fhi.x, fhi.y);
}

__global__ void __launch_bounds__(1024, 1)
ngram_sum_kernel(const int* __restrict__ x,
                 const float* __restrict__ bvec,
                 float* __restrict__ out) {
    extern __shared__ char smem[];
    uint2* sT = reinterpret_cast<uint2*>(smem);             // table, 32 uint2/row
    int*   sx = reinterpret_cast<int*>(smem + TBL_BYTES);   // token window

    const int tid = threadIdx.x;
    const int pos_base = blockIdx.x * POS_PER_CTA;
    const int b      = pos_base >> 12;                      // batch row
    const int j_base = pos_base & (LL - 1);                 // row offset

    // --- Prologue: copy table (8192 uint4, 8 per thread, coalesced) ---
    {
        const uint4* gT = reinterpret_cast<const uint4*>(g_Th);
        uint4* dT = reinterpret_cast<uint4*>(smem);
#pragma unroll
        for (int i = 0; i < 8; i++)
            dT[i * 1024 + tid] = __ldg(&gT[i * 1024 + tid]);
    }
    // --- Token window: x[b][j_base-4 .. j_base+1023], ALL 1028 slots
    //     (strided loop covers indices >= blockDim). Clamped at row start;
    //     clamped slots only indexed by bias-only positions, never consumed. ---
    for (int idx = tid; idx < TOK_COUNT; idx += 1024) {
        int off = j_base - NN1 + idx;
        if (off < 0) off = 0;
        sx[idx] = __ldg(x + b * LL + off);
    }
    __syncthreads();

    // --- Main loop: warp w owns local positions [w*32, w*32+32) = 16 pairs ---
    const int wid  = tid >> 5;                  // 0..31
    const int lane = tid & 31;

    float4* obase = reinterpret_cast<float4*>(out + (size_t)pos_base * VV)
                    + (size_t)wid * 32 * 32;    // 32 positions * 32 float4

#pragma unroll 4
    for (int i = 0; i < 16; i++) {
        const int jl = (wid << 5) + (i << 1);   // local even position index
        float4* o = obase + (size_t)(i << 1) * 32;

        if (j_base + jl < NN1) {                // bias-only (start of each row)
            float4 bb = reinterpret_cast<const float4*>(bvec)[lane];
            o[lane]      = bb;
            o[32 + lane] = bb;
            continue;
        }
        // sx[idx] = x[b][j_base - 4 + idx]; position (j_base+jl) uses
        // sx[jl..jl+3], position (j_base+jl+1) uses sx[jl+1..jl+4].
        const int t0 = sx[jl + 0];
        const int t1 = sx[jl + 1];
        const int t2 = sx[jl + 2];
        const int t3 = sx[jl + 3];
        const int t4 = sx[jl + 4];

        uint2 a0 = sT[((0 * VV + t0) << 5) + lane];
        uint2 a1 = sT[((1 * VV + t1) << 5) + lane];
        uint2 a2 = sT[((2 * VV + t2) << 5) + lane];
        uint2 a3 = sT[((3 * VV + t3) << 5) + lane];
        uint2 c0 = sT[((0 * VV + t1) << 5) + lane];
        uint2 c1 = sT[((1 * VV + t2) << 5) + lane];
        uint2 c2 = sT[((2 * VV + t3) << 5) + lane];
        uint2 c3 = sT[((3 * VV + t4) << 5) + lane];

        o[lane]      = combine4(a0, a1, a2, a3);
        o[32 + lane] = combine4(c0, c1, c2, c3);
    }
}

// ---------------------------------------------------------------------------
// Launch. Inputs (metadata order): x(int32 B*L), emb(f32 V*D), W(f32 V*4D),
// b(f32 V). Output: f32 B*L*V.
// ---------------------------------------------------------------------------
extern "C" void kernel_launch(void* const* d_in, const int* in_sizes, int n_in,
                              void* d_out, int out_size) {
    const int*   x    = (const int*)d_in[0];
    const float* emb  = (const float*)d_in[1];
    const float* W    = (const float*)d_in[2];
    const float* bvec = (const float*)d_in[3];
    float* out = (float*)d_out;

    // Opt in to >48KB dynamic smem. Host-side attribute set, idempotent and
    // deterministic (no static guards — called every invocation).
    cudaFuncSetAttribute(ngram_sum_kernel,
                         cudaFuncAttributeMaxDynamicSharedMemorySize,
                         SMEM_BYTES);

    dim3 bgrid(VV / VPB, VV / TPB, NN1);        // (8, 16, 4) = 512 blocks
    build_table_kernel<<<bgrid, 128>>>(emb, W, bvec);

    ngram_sum_kernel<<<NGRAM_CTAS, 1024, SMEM_BYTES>>>(x, bvec, out);
}